// round 5
// baseline (speedup 1.0000x reference)
#include <cuda_runtime.h>
#include <cuda_bf16.h>

// Problem constants (KnowledgeRetriever: query [4,1024,512] f32, knowledge [64,512] f32).
// Reference takes top-64 of an argsort over 64 -> ALL indices -> mean over all
// knowledge rows. Output = broadcast of column-mean(knowledge) to every (b,s).
#define E        512            // embedding dim
#define KROWS    64             // knowledge rows
#define E4       (E / 4)        // 128 float4 per row
#define OUT_F    (4 * 1024 * 512)       // 2,097,152 floats
#define OUT_F4   (OUT_F / 4)            // 524,288 float4
#define BCAST_BLOCKS   1024
#define BCAST_THREADS  256
#define BCAST_STRIDE   (BCAST_BLOCKS * BCAST_THREADS)   // 262144, multiple of E4

__device__ float4 g_mean4[E4];

// Kernel A: column mean of knowledge [64, 512] -> g_mean4 [128 float4].
// 512 threads: thread t owns float4-column (t & 127) over row-group (t >> 7).
__global__ void kr_mean_kernel(const float* __restrict__ knowledge) {
    __shared__ float4 part[4][E4];
    const float4* __restrict__ k4 = reinterpret_cast<const float4*>(knowledge);

    int t  = threadIdx.x;
    int c4 = t & (E4 - 1);
    int h  = t >> 7;          // 0..3, each covers 16 rows

    float4 s = make_float4(0.f, 0.f, 0.f, 0.f);
#pragma unroll
    for (int r = 0; r < 16; r++) {
        float4 v = k4[(h * 16 + r) * E4 + c4];
        s.x += v.x; s.y += v.y; s.z += v.z; s.w += v.w;
    }
    part[h][c4] = s;
    __syncthreads();

    if (t < E4) {
        float4 a = part[0][t], b = part[1][t], c = part[2][t], d = part[3][t];
        const float inv = 1.0f / (float)KROWS;
        float4 m;
        m.x = (a.x + b.x + c.x + d.x) * inv;
        m.y = (a.y + b.y + c.y + d.y) * inv;
        m.z = (a.z + b.z + c.z + d.z) * inv;
        m.w = (a.w + b.w + c.w + d.w) * inv;
        g_mean4[t] = m;
    }
}

// Kernel B: broadcast g_mean4 across all 4096 output rows.
// gid stride (262144) is a multiple of E4 (128), so each thread's float4-column
// index (gid & 127) is invariant -> hoist one L1-broadcast load, then pure STG.128.
__global__ void __launch_bounds__(BCAST_THREADS)
kr_bcast_kernel(float4* __restrict__ out) {
    int gid = blockIdx.x * BCAST_THREADS + threadIdx.x;
    float4 v = g_mean4[gid & (E4 - 1)];
#pragma unroll
    for (int i = gid; i < OUT_F4; i += BCAST_STRIDE)
        out[i] = v;
}

extern "C" void kernel_launch(void* const* d_in, const int* in_sizes, int n_in,
                              void* d_out, int out_size) {
    // d_in[0]: query_embedding [4,1024,512] f32 (unused — dead code in reference)
    // d_in[1]: knowledge       [64,512]     f32
    const float* knowledge = (const float*)d_in[1];
    float4* out4 = (float4*)d_out;

    kr_mean_kernel<<<1, 512>>>(knowledge);
    kr_bcast_kernel<<<BCAST_BLOCKS, BCAST_THREADS>>>(out4);
}

// round 7
// speedup vs baseline: 1.2977x; 1.2977x over previous
#include <cuda_runtime.h>
#include <cuda_bf16.h>

// KnowledgeRetriever: query [4,1024,512] f32 (dead code), knowledge [64,512] f32.
// Reference's top-64-of-64 argsort selects ALL rows -> output is column-mean of
// knowledge broadcast to every (b,s). Fused single-wave kernel:
//   grid (4 colgroups x 32 rowgroups) = 128 blocks, 256 threads.
//   Each block: mean of its 32 float4-columns (32KB read), then stores a
//   128-row x 32-float4 tile of the output (64KB write).

#define E4        128                   // float4 per row (E=512)
#define KROWS     64
#define OUT_ROWS  4096                  // 4*1024
#define COLS_PER_BLK   32               // float4 columns per block
#define ROWS_PER_BLK   128              // output rows per block (4096/32)
#define THREADS   256

__global__ void __launch_bounds__(THREADS)
kr_fused_kernel(const float* __restrict__ knowledge, float4* __restrict__ out) {
    __shared__ float4 part[8][COLS_PER_BLK];
    __shared__ float4 mean_s[COLS_PER_BLK];

    const float4* __restrict__ k4 = reinterpret_cast<const float4*>(knowledge);

    const int t       = threadIdx.x;
    const int lane    = t & 31;                 // column within slice
    const int w       = t >> 5;                 // warp id 0..7
    const int colbase = blockIdx.x * COLS_PER_BLK;   // 0,32,64,96
    const int rowbase = blockIdx.y * ROWS_PER_BLK;   // output row base

    // ---- Mean phase: sum 8 knowledge rows per thread over this column slice.
    {
        float4 s = make_float4(0.f, 0.f, 0.f, 0.f);
        const int r0 = w * 8;                   // rows r0..r0+7
#pragma unroll
        for (int r = 0; r < 8; r++) {
            float4 v = k4[(size_t)(r0 + r) * E4 + colbase + lane];
            s.x += v.x; s.y += v.y; s.z += v.z; s.w += v.w;
        }
        part[w][lane] = s;
    }
    __syncthreads();

    if (t < COLS_PER_BLK) {
        float4 m = make_float4(0.f, 0.f, 0.f, 0.f);
#pragma unroll
        for (int g = 0; g < 8; g++) {
            float4 p = part[g][t];
            m.x += p.x; m.y += p.y; m.z += p.z; m.w += p.w;
        }
        const float inv = 1.0f / (float)KROWS;
        m.x *= inv; m.y *= inv; m.z *= inv; m.w *= inv;
        mean_s[t] = m;
    }
    __syncthreads();

    // ---- Store phase: warp w writes rows rowbase+w, +8, ... (16 rows),
    // 512B contiguous per row (lanes cover 32 consecutive float4).
    const float4 v = mean_s[lane];
#pragma unroll
    for (int r = 0; r < ROWS_PER_BLK / 8; r++) {
        const int row = rowbase + w + r * 8;
        out[(size_t)row * E4 + colbase + lane] = v;
    }
}

extern "C" void kernel_launch(void* const* d_in, const int* in_sizes, int n_in,
                              void* d_out, int out_size) {
    // d_in[0]: query_embedding (unused — dead code in reference)
    // d_in[1]: knowledge [64,512] f32
    const float* knowledge = (const float*)d_in[1];
    float4* out4 = (float4*)d_out;

    dim3 grid(E4 / COLS_PER_BLK, OUT_ROWS / ROWS_PER_BLK);   // (4, 32)
    kr_fused_kernel<<<grid, THREADS>>>(knowledge, out4);
}